// round 1
// baseline (speedup 1.0000x reference)
#include <cuda_runtime.h>
#include <cstdint>

// Problem constants (fixed by setup_inputs)
#define BMAX 16384
#define E_CNT 20

// Scratch (allocation-free rule: __device__ globals)
__device__ float g_agg[BMAX * 5 * 128];        // 40 MB
__device__ float g_h[(size_t)BMAX * 5 * 512];  // 160 MB  (h1 || h2 per row)

// ---------------------------------------------------------------------------
// K1: edge MLP + aggregation.
//   For each batch b: inp_mp (20 x 46) -> relu(inp_mp @ mp_w + mp_b) (20 x 128)
//   accumulate into agg[b][dst][128].
// grid.x = B/8, 256 threads. Thread t: nb = t&31 (4 output cols), bl = t>>5 (b).
// ---------------------------------------------------------------------------
__global__ __launch_bounds__(256) void k_edge(
    const float* __restrict__ obs, const float* __restrict__ act,
    const float* __restrict__ ag,  const float* __restrict__ g,
    const float* __restrict__ mp_w, const float* __restrict__ mp_b)
{
    extern __shared__ float smem[];
    float* sw   = smem;              // 46*128
    float* sinp = smem + 46 * 128;   // 8*20*48 (padded 46->48)
    const int t  = threadIdx.x;
    const int b0 = blockIdx.x * 8;

    for (int i = t; i < 46 * 128; i += 256) sw[i] = mp_w[i];

    for (int idx = t; idx < 8 * 20 * 46; idx += 256) {
        int bl  = idx / 920;
        int rem = idx - bl * 920;
        int e   = rem / 46;
        int k   = rem - e * 46;
        int src = e >> 2, rr = e & 3;
        int dst = (rr < src) ? rr : rr + 1;
        int b   = b0 + bl;
        float v;
        if (k < 10)       v = obs[b * 85 + k];                       // obs_body
        else if (k < 14)  v = act[b * 4 + (k - 10)];                 // act
        else if (k == 14) v = g[b * 30 + e]      - ag[b * 30 + e];   // dg[pred0]
        else if (k == 15) v = g[b * 30 + e + 10] - ag[b * 30 + e + 10]; // dg[pred1]
        else if (k < 31)  v = obs[b * 85 + 10 + src * 15 + (k - 16)]; // src obj
        else              v = obs[b * 85 + 10 + dst * 15 + (k - 31)]; // dst obj
        sinp[(bl * 20 + e) * 48 + k] = v;
    }
    __syncthreads();

    const int nb = t & 31;
    const int bl = t >> 5;
    const int n0 = nb * 4;
    const float4 bias = *reinterpret_cast<const float4*>(mp_b + n0);
    const float4* sw4 = reinterpret_cast<const float4*>(sw);
    const float* ip = sinp + bl * 20 * 48;

    float acc[5][4];
#pragma unroll
    for (int i = 0; i < 5; i++)
#pragma unroll
        for (int c = 0; c < 4; c++) acc[i][c] = 0.0f;

#pragma unroll
    for (int e = 0; e < 20; e++) {
        const int src = e >> 2, rr = e & 3;
        const int dst = (rr < src) ? rr : rr + 1;  // compile-time after unroll
        float4 s = bias;
        const float* ipe = ip + e * 48;
#pragma unroll 2
        for (int k = 0; k < 46; k++) {
            float  a = ipe[k];
            float4 w = sw4[k * 32 + nb];
            s.x += a * w.x; s.y += a * w.y; s.z += a * w.z; s.w += a * w.w;
        }
        acc[dst][0] += fmaxf(s.x, 0.0f);
        acc[dst][1] += fmaxf(s.y, 0.0f);
        acc[dst][2] += fmaxf(s.z, 0.0f);
        acc[dst][3] += fmaxf(s.w, 0.0f);
    }

    const int b = b0 + bl;
#pragma unroll
    for (int i = 0; i < 5; i++) {
        float4 o = make_float4(acc[i][0], acc[i][1], acc[i][2], acc[i][3]);
        *reinterpret_cast<float4*>(&g_agg[(size_t)(b * 5 + i) * 128 + n0]) = o;
    }
}

// ---------------------------------------------------------------------------
// K2: h = relu(inp @ [W1|W3] + [b1|b3]),  inp = [act(4), body(10), obj(15), agg(128)]
// grid (B/16, 4 N-chunks of 128), 256 threads as 16(ty: b) x 16(tx: 8 cols).
// Thread computes 5 rows (the 5 objects of its b) x 8 cols.
// ---------------------------------------------------------------------------
#define SA_S 164
__global__ __launch_bounds__(256) void k_phi1(
    const float* __restrict__ obs, const float* __restrict__ act,
    const float* __restrict__ phi_w1, const float* __restrict__ phi_b1,
    const float* __restrict__ phi_w3, const float* __restrict__ phi_b3)
{
    extern __shared__ float smem[];
    float* sa  = smem;               // 80 x SA_S
    float* swt = smem + 80 * SA_S;   // 157 x 128
    const int t     = threadIdx.x;
    const int b0    = blockIdx.x * 16;
    const int chunk = blockIdx.y;
    const float* wsrc = (chunk < 2) ? (phi_w1 + chunk * 128) : (phi_w3 + (chunk - 2) * 128);
    const float* bsrc = (chunk < 2) ? (phi_b1 + chunk * 128) : (phi_b3 + (chunk - 2) * 128);

    for (int idx = t; idx < 157 * 128; idx += 256) {
        int r = idx >> 7, c = idx & 127;
        swt[idx] = wsrc[r * 256 + c];
    }
    for (int idx = t; idx < 80 * 157; idx += 256) {
        int r = idx / 157;
        int k = idx - r * 157;
        int bq = r / 5;
        int n  = r - bq * 5;
        int b  = b0 + bq;
        float v;
        if (k < 4)       v = act[b * 4 + k];                       // ba: act first!
        else if (k < 14) v = obs[b * 85 + (k - 4)];                // then body
        else if (k < 29) v = obs[b * 85 + 10 + n * 15 + (k - 14)]; // obj n
        else             v = g_agg[(size_t)(b * 5 + n) * 128 + (k - 29)];
        sa[r * SA_S + k] = v;
    }
    __syncthreads();

    const int tx = t & 15, ty = t >> 4;
    const float4* sw4 = reinterpret_cast<const float4*>(swt);
    const float* arow = sa + ty * 5 * SA_S;

    float acc[5][8];
#pragma unroll
    for (int i = 0; i < 5; i++)
#pragma unroll
        for (int c = 0; c < 8; c++) acc[i][c] = 0.0f;

#pragma unroll 2
    for (int k = 0; k < 157; k++) {
        float a[5];
#pragma unroll
        for (int i = 0; i < 5; i++) a[i] = arow[i * SA_S + k];
        float4 w0 = sw4[k * 32 + tx * 2];
        float4 w1 = sw4[k * 32 + tx * 2 + 1];
        float w[8] = {w0.x, w0.y, w0.z, w0.w, w1.x, w1.y, w1.z, w1.w};
#pragma unroll
        for (int i = 0; i < 5; i++)
#pragma unroll
            for (int c = 0; c < 8; c++) acc[i][c] += a[i] * w[c];
    }

    const int c0 = tx * 8;
    float bb[8];
#pragma unroll
    for (int c = 0; c < 8; c++) bb[c] = bsrc[c0 + c];
#pragma unroll
    for (int i = 0; i < 5; i++) {
        size_t row = (size_t)(b0 + ty) * 5 + i;
        float4 o0 = make_float4(fmaxf(acc[i][0] + bb[0], 0.f), fmaxf(acc[i][1] + bb[1], 0.f),
                                fmaxf(acc[i][2] + bb[2], 0.f), fmaxf(acc[i][3] + bb[3], 0.f));
        float4 o1 = make_float4(fmaxf(acc[i][4] + bb[4], 0.f), fmaxf(acc[i][5] + bb[5], 0.f),
                                fmaxf(acc[i][6] + bb[6], 0.f), fmaxf(acc[i][7] + bb[7], 0.f));
        float* dst = &g_h[row * 512 + chunk * 128 + c0];
        *reinterpret_cast<float4*>(dst)     = o0;
        *reinterpret_cast<float4*>(dst + 4) = o1;
    }
}

// ---------------------------------------------------------------------------
// K3: o = relu(h @ W2 + b2); q[b] = sum_{n,j} o * rho[j] + rho_b  (per branch)
// grid (B/16, 2 branches), 256 threads (16x16). N=256 processed as 2 chunks
// of 128 (W chunk staged in smem). Epilogue fused; single writer per (b,branch).
// ---------------------------------------------------------------------------
#define SH_S 260
__global__ __launch_bounds__(256) void k_phi2(
    const float* __restrict__ phi_w2, const float* __restrict__ phi_b2,
    const float* __restrict__ phi_w4, const float* __restrict__ phi_b4,
    const float* __restrict__ rho_w1, const float* __restrict__ rho_b1,
    const float* __restrict__ rho_w2, const float* __restrict__ rho_b2,
    float* __restrict__ out, int B)
{
    extern __shared__ float smem[];
    float* sh  = smem;               // 80 x SH_S
    float* swt = smem + 80 * SH_S;   // 256 x 128
    const int t  = threadIdx.x;
    const int b0 = blockIdx.x * 16;
    const int br = blockIdx.y;
    const float* W    = br ? phi_w4 : phi_w2;
    const float* bias = br ? phi_b4 : phi_b2;
    const float* rho  = br ? rho_w2 : rho_w1;
    const float  rb   = br ? rho_b2[0] : rho_b1[0];

    for (int idx = t; idx < 80 * 256; idx += 256) {
        int r = idx >> 8, k = idx & 255;
        sh[r * SH_S + k] = g_h[((size_t)b0 * 5 + r) * 512 + br * 256 + k];
    }

    const int tx = t & 15, ty = t >> 4;
    const float* arow = sh + ty * 5 * SH_S;
    float q = 0.0f;

    for (int chunk = 0; chunk < 2; chunk++) {
        __syncthreads();  // h-tile ready (chunk 0) / prev W readers done (chunk 1)
        for (int idx = t; idx < 256 * 128; idx += 256) {
            int r = idx >> 7, c = idx & 127;
            swt[idx] = W[r * 256 + chunk * 128 + c];
        }
        __syncthreads();

        const float4* sw4 = reinterpret_cast<const float4*>(swt);
        float acc[5][8];
#pragma unroll
        for (int i = 0; i < 5; i++)
#pragma unroll
            for (int c = 0; c < 8; c++) acc[i][c] = 0.0f;

#pragma unroll 2
        for (int k = 0; k < 256; k++) {
            float a[5];
#pragma unroll
            for (int i = 0; i < 5; i++) a[i] = arow[i * SH_S + k];
            float4 w0 = sw4[k * 32 + tx * 2];
            float4 w1 = sw4[k * 32 + tx * 2 + 1];
            float w[8] = {w0.x, w0.y, w0.z, w0.w, w1.x, w1.y, w1.z, w1.w};
#pragma unroll
            for (int i = 0; i < 5; i++)
#pragma unroll
                for (int c = 0; c < 8; c++) acc[i][c] += a[i] * w[c];
        }

        const int c0 = chunk * 128 + tx * 8;
#pragma unroll
        for (int c = 0; c < 8; c++) {
            float bj = bias[c0 + c], rj = rho[c0 + c];
#pragma unroll
            for (int i = 0; i < 5; i++)
                q += fmaxf(acc[i][c] + bj, 0.0f) * rj;
        }
    }

    // reduce over the 16 tx lanes of this b (width-16 shfl: stays in-group)
#pragma unroll
    for (int off = 8; off; off >>= 1)
        q += __shfl_down_sync(0xffffffffu, q, off, 16);
    if (tx == 0) out[br * B + (b0 + ty)] = q + rb;
}

// ---------------------------------------------------------------------------
extern "C" void kernel_launch(void* const* d_in, const int* in_sizes, int n_in,
                              void* d_out, int out_size)
{
    const float* obs    = (const float*)d_in[0];
    const float* act    = (const float*)d_in[1];
    const float* ag     = (const float*)d_in[2];
    const float* g      = (const float*)d_in[3];
    const float* mp_w   = (const float*)d_in[4];
    const float* mp_b   = (const float*)d_in[5];
    const float* phi_w1 = (const float*)d_in[6];
    const float* phi_b1 = (const float*)d_in[7];
    const float* phi_w2 = (const float*)d_in[8];
    const float* phi_b2 = (const float*)d_in[9];
    const float* phi_w3 = (const float*)d_in[10];
    const float* phi_b3 = (const float*)d_in[11];
    const float* phi_w4 = (const float*)d_in[12];
    const float* phi_b4 = (const float*)d_in[13];
    const float* rho_w1 = (const float*)d_in[14];
    const float* rho_b1 = (const float*)d_in[15];
    const float* rho_w2 = (const float*)d_in[16];
    const float* rho_b2 = (const float*)d_in[17];
    float* out = (float*)d_out;

    const int B = in_sizes[1] / 4;  // act is (B,4)

    const int S1 = (46 * 128 + 8 * 20 * 48) * 4;      // 54,272 B
    const int S2 = (80 * SA_S + 157 * 128) * 4;       // 132,864 B
    const int S3 = (80 * SH_S + 256 * 128) * 4;       // 214,272 B
    cudaFuncSetAttribute(k_edge, cudaFuncAttributeMaxDynamicSharedMemorySize, S1);
    cudaFuncSetAttribute(k_phi1, cudaFuncAttributeMaxDynamicSharedMemorySize, S2);
    cudaFuncSetAttribute(k_phi2, cudaFuncAttributeMaxDynamicSharedMemorySize, S3);

    k_edge<<<B / 8, 256, S1>>>(obs, act, ag, g, mp_w, mp_b);
    k_phi1<<<dim3(B / 16, 4), 256, S2>>>(obs, act, phi_w1, phi_b1, phi_w3, phi_b3);
    k_phi2<<<dim3(B / 16, 2), 256, S3>>>(phi_w2, phi_b2, phi_w4, phi_b4,
                                         rho_w1, rho_b1, rho_w2, rho_b2, out, B);
}

// round 3
// speedup vs baseline: 1.2012x; 1.2012x over previous
#include <cuda_runtime.h>
#include <cuda_bf16.h>
#include <cstdint>

// Problem constants (fixed by setup_inputs)
#define BMAX 16384

// Scratch (allocation-free rule: __device__ globals)
__device__ float g_agg[BMAX * 5 * 128];        // 40 MB
__device__ float g_h[(size_t)BMAX * 5 * 512];  // 160 MB  (h1 || h2 per row)

// ============================================================================
// Warp-MMA helpers (sm_80-era PTX: legal on compute_103, maps to HMMA)
// ============================================================================
#define LDSM_X4(r0, r1, r2, r3, addr) \
    asm volatile("ldmatrix.sync.aligned.m8n8.x4.shared.b16 {%0,%1,%2,%3}, [%4];" \
        : "=r"(r0), "=r"(r1), "=r"(r2), "=r"(r3) : "r"(addr))

__device__ __forceinline__ void mma16816(float* d, const uint32_t* a, const uint32_t* b) {
    asm volatile(
        "mma.sync.aligned.m16n8k16.row.col.f32.bf16.bf16.f32 "
        "{%0,%1,%2,%3}, {%4,%5,%6,%7}, {%8,%9}, {%0,%1,%2,%3};"
        : "+f"(d[0]), "+f"(d[1]), "+f"(d[2]), "+f"(d[3])
        : "r"(a[0]), "r"(a[1]), "r"(a[2]), "r"(a[3]), "r"(b[0]), "r"(b[1]));
}

__device__ __forceinline__ uint32_t smem_u32(const void* p) {
    uint32_t a;
    asm("{ .reg .u64 tmp; cvta.to.shared.u64 tmp, %1; cvt.u32.u64 %0, tmp; }"
        : "=r"(a) : "l"(p));
    return a;
}

// ---------------------------------------------------------------------------
// K1: edge MLP + aggregation (unchanged — validated)
// ---------------------------------------------------------------------------
__global__ __launch_bounds__(256) void k_edge(
    const float* __restrict__ obs, const float* __restrict__ act,
    const float* __restrict__ ag,  const float* __restrict__ g,
    const float* __restrict__ mp_w, const float* __restrict__ mp_b)
{
    extern __shared__ float smem[];
    float* sw   = smem;              // 46*128
    float* sinp = smem + 46 * 128;   // 8*20*48 (padded 46->48)
    const int t  = threadIdx.x;
    const int b0 = blockIdx.x * 8;

    for (int i = t; i < 46 * 128; i += 256) sw[i] = mp_w[i];

    for (int idx = t; idx < 8 * 20 * 46; idx += 256) {
        int bl  = idx / 920;
        int rem = idx - bl * 920;
        int e   = rem / 46;
        int k   = rem - e * 46;
        int src = e >> 2, rr = e & 3;
        int dst = (rr < src) ? rr : rr + 1;
        int b   = b0 + bl;
        float v;
        if (k < 10)       v = obs[b * 85 + k];
        else if (k < 14)  v = act[b * 4 + (k - 10)];
        else if (k == 14) v = g[b * 30 + e]      - ag[b * 30 + e];
        else if (k == 15) v = g[b * 30 + e + 10] - ag[b * 30 + e + 10];
        else if (k < 31)  v = obs[b * 85 + 10 + src * 15 + (k - 16)];
        else              v = obs[b * 85 + 10 + dst * 15 + (k - 31)];
        sinp[(bl * 20 + e) * 48 + k] = v;
    }
    __syncthreads();

    const int nb = t & 31;
    const int bl = t >> 5;
    const int n0 = nb * 4;
    const float4 bias = *reinterpret_cast<const float4*>(mp_b + n0);
    const float4* sw4 = reinterpret_cast<const float4*>(sw);
    const float* ip = sinp + bl * 20 * 48;

    float acc[5][4];
#pragma unroll
    for (int i = 0; i < 5; i++)
#pragma unroll
        for (int c = 0; c < 4; c++) acc[i][c] = 0.0f;

#pragma unroll
    for (int e = 0; e < 20; e++) {
        const int src = e >> 2, rr = e & 3;
        const int dst = (rr < src) ? rr : rr + 1;
        float4 s = bias;
        const float* ipe = ip + e * 48;
#pragma unroll 2
        for (int k = 0; k < 46; k++) {
            float  a = ipe[k];
            float4 w = sw4[k * 32 + nb];
            s.x += a * w.x; s.y += a * w.y; s.z += a * w.z; s.w += a * w.w;
        }
        acc[dst][0] += fmaxf(s.x, 0.0f);
        acc[dst][1] += fmaxf(s.y, 0.0f);
        acc[dst][2] += fmaxf(s.z, 0.0f);
        acc[dst][3] += fmaxf(s.w, 0.0f);
    }

    const int b = b0 + bl;
#pragma unroll
    for (int i = 0; i < 5; i++) {
        float4 o = make_float4(acc[i][0], acc[i][1], acc[i][2], acc[i][3]);
        *reinterpret_cast<float4*>(&g_agg[(size_t)(b * 5 + i) * 128 + n0]) = o;
    }
}

// ---------------------------------------------------------------------------
// K2: h = relu(inp @ [W1|W3] + [b1|b3]) (unchanged — validated)
// ---------------------------------------------------------------------------
#define SA_S 164
__global__ __launch_bounds__(256) void k_phi1(
    const float* __restrict__ obs, const float* __restrict__ act,
    const float* __restrict__ phi_w1, const float* __restrict__ phi_b1,
    const float* __restrict__ phi_w3, const float* __restrict__ phi_b3)
{
    extern __shared__ float smem[];
    float* sa  = smem;               // 80 x SA_S
    float* swt = smem + 80 * SA_S;   // 157 x 128
    const int t     = threadIdx.x;
    const int b0    = blockIdx.x * 16;
    const int chunk = blockIdx.y;
    const float* wsrc = (chunk < 2) ? (phi_w1 + chunk * 128) : (phi_w3 + (chunk - 2) * 128);
    const float* bsrc = (chunk < 2) ? (phi_b1 + chunk * 128) : (phi_b3 + (chunk - 2) * 128);

    for (int idx = t; idx < 157 * 128; idx += 256) {
        int r = idx >> 7, c = idx & 127;
        swt[idx] = wsrc[r * 256 + c];
    }
    for (int idx = t; idx < 80 * 157; idx += 256) {
        int r = idx / 157;
        int k = idx - r * 157;
        int bq = r / 5;
        int n  = r - bq * 5;
        int b  = b0 + bq;
        float v;
        if (k < 4)       v = act[b * 4 + k];
        else if (k < 14) v = obs[b * 85 + (k - 4)];
        else if (k < 29) v = obs[b * 85 + 10 + n * 15 + (k - 14)];
        else             v = g_agg[(size_t)(b * 5 + n) * 128 + (k - 29)];
        sa[r * SA_S + k] = v;
    }
    __syncthreads();

    const int tx = t & 15, ty = t >> 4;
    const float4* sw4 = reinterpret_cast<const float4*>(swt);
    const float* arow = sa + ty * 5 * SA_S;

    float acc[5][8];
#pragma unroll
    for (int i = 0; i < 5; i++)
#pragma unroll
        for (int c = 0; c < 8; c++) acc[i][c] = 0.0f;

#pragma unroll 2
    for (int k = 0; k < 157; k++) {
        float a[5];
#pragma unroll
        for (int i = 0; i < 5; i++) a[i] = arow[i * SA_S + k];
        float4 w0 = sw4[k * 32 + tx * 2];
        float4 w1 = sw4[k * 32 + tx * 2 + 1];
        float w[8] = {w0.x, w0.y, w0.z, w0.w, w1.x, w1.y, w1.z, w1.w};
#pragma unroll
        for (int i = 0; i < 5; i++)
#pragma unroll
            for (int c = 0; c < 8; c++) acc[i][c] += a[i] * w[c];
    }

    const int c0 = tx * 8;
    float bb[8];
#pragma unroll
    for (int c = 0; c < 8; c++) bb[c] = bsrc[c0 + c];
#pragma unroll
    for (int i = 0; i < 5; i++) {
        size_t row = (size_t)(b0 + ty) * 5 + i;
        float4 o0 = make_float4(fmaxf(acc[i][0] + bb[0], 0.f), fmaxf(acc[i][1] + bb[1], 0.f),
                                fmaxf(acc[i][2] + bb[2], 0.f), fmaxf(acc[i][3] + bb[3], 0.f));
        float4 o1 = make_float4(fmaxf(acc[i][4] + bb[4], 0.f), fmaxf(acc[i][5] + bb[5], 0.f),
                                fmaxf(acc[i][6] + bb[6], 0.f), fmaxf(acc[i][7] + bb[7], 0.f));
        float* dst = &g_h[row * 512 + chunk * 128 + c0];
        *reinterpret_cast<float4*>(dst)     = o0;
        *reinterpret_cast<float4*>(dst + 4) = o1;
    }
}

// ---------------------------------------------------------------------------
// K-init: out[b] = rho_b (phi2 epilogue atomically accumulates onto it)
// ---------------------------------------------------------------------------
__global__ void k_init(float* __restrict__ out,
                       const float* __restrict__ rb1, const float* __restrict__ rb2, int B)
{
    int i = blockIdx.x * 256 + threadIdx.x;
    if (i < B) { out[i] = rb1[0]; out[B + i] = rb2[0]; }
}

// ---------------------------------------------------------------------------
// K3 (warp MMA, bf16 3-split): CTA computes D[128m x 128n] = h-tile @ W-half,
// K=256 in 4 chunks of 64. 8 warps as 4(M) x 2(N); warp tile m32 x n64.
// Fused epilogue: q += sum relu(D + bias) * rho -> atomicAdd per b.
//
// SMEM (bytes): bias 0..512, rho 512..1024, s_arr 1024..1536,
//   A_hi 1536 (+18432), A_lo 19968, B_hi 38400, B_lo 56832; total 75264.
// A/B tiles: [128 rows][64 k] bf16, row stride 72 elems (144 B) -> ldmatrix
// conflict-free (rows hit distinct bank quads).
// ---------------------------------------------------------------------------
#define SB_BIAS 0
#define SB_RHO  512
#define SB_SARR 1024
#define SB_AHI  1536
#define SB_ALO  19968
#define SB_BHI  38400
#define SB_BLO  56832
#define P2_SMEM 75264

__global__ __launch_bounds__(256) void k_phi2_mma(
    const float* __restrict__ phi_w2, const float* __restrict__ phi_b2,
    const float* __restrict__ phi_w4, const float* __restrict__ phi_b4,
    const float* __restrict__ rho_w1, const float* __restrict__ rho_w2,
    float* __restrict__ out, int B)
{
    extern __shared__ char smemc[];
    const uint32_t sbase = smem_u32(smemc);
    const int t    = threadIdx.x;
    const int wid  = t >> 5;
    const int lane = t & 31;
    const int m0   = blockIdx.x * 128;   // global row = b*5 + obj
    const int br   = blockIdx.y;
    const int nc   = blockIdx.z;         // which 128-col half of N=256

    const float* W    = br ? phi_w4 : phi_w2;
    const float* bias = br ? phi_b4 : phi_b2;
    const float* rho  = br ? rho_w2 : rho_w1;

    float* sb    = reinterpret_cast<float*>(smemc + SB_BIAS);
    float* sr    = reinterpret_cast<float*>(smemc + SB_RHO);
    float* s_arr = reinterpret_cast<float*>(smemc + SB_SARR);

    if (t < 128) {
        sb[t] = bias[nc * 128 + t];
        sr[t] = rho[nc * 128 + t];
        s_arr[t] = 0.0f;
    }

    const int warp_m = wid & 3;   // 4 x 32 rows
    const int warp_n = wid >> 2;  // 2 x 64 cols

    float acc[2][8][4];
#pragma unroll
    for (int mt = 0; mt < 2; mt++)
#pragma unroll
        for (int nt = 0; nt < 8; nt++)
#pragma unroll
            for (int j = 0; j < 4; j++) acc[mt][nt][j] = 0.0f;

    // ldmatrix lane->address mapping (constant across chunks/ksteps)
    const int a_row  = warp_m * 32 + (lane & 15);     // + mt*16
    const int a_ksub = (lane >> 4) * 8;               // + ks*16
    const int b_row  = warp_n * 64 + (lane & 7) + ((lane >> 4) & 1) * 8;  // + pair*16
    const int b_ksub = ((lane >> 3) & 1) * 8;         // + ks*16

    for (int kc = 0; kc < 4; kc++) {
        __syncthreads();  // prior chunk's MMA reads done (or initial stores visible)

        // --- stage A chunk: h[m0..m0+128, br*256 + kc*64 ..+64] -> bf16 hi/lo ---
        for (int idx = t; idx < 128 * 16; idx += 256) {
            int row = idx >> 4;
            int k0  = (idx & 15) * 4;
            float4 v = *reinterpret_cast<const float4*>(
                &g_h[(size_t)(m0 + row) * 512 + br * 256 + kc * 64 + k0]);
            __nv_bfloat16 hx = __float2bfloat16_rn(v.x);
            __nv_bfloat16 hy = __float2bfloat16_rn(v.y);
            __nv_bfloat16 hz = __float2bfloat16_rn(v.z);
            __nv_bfloat16 hw = __float2bfloat16_rn(v.w);
            __nv_bfloat16 lx = __float2bfloat16_rn(v.x - __bfloat162float(hx));
            __nv_bfloat16 ly = __float2bfloat16_rn(v.y - __bfloat162float(hy));
            __nv_bfloat16 lz = __float2bfloat16_rn(v.z - __bfloat162float(hz));
            __nv_bfloat16 lw = __float2bfloat16_rn(v.w - __bfloat162float(hw));
            uint32_t off = (uint32_t)(row * 144 + k0 * 2);
            uint32_t hi0 = ((uint32_t)__bfloat16_as_ushort(hy) << 16) | __bfloat16_as_ushort(hx);
            uint32_t hi1 = ((uint32_t)__bfloat16_as_ushort(hw) << 16) | __bfloat16_as_ushort(hz);
            uint32_t lo0 = ((uint32_t)__bfloat16_as_ushort(ly) << 16) | __bfloat16_as_ushort(lx);
            uint32_t lo1 = ((uint32_t)__bfloat16_as_ushort(lw) << 16) | __bfloat16_as_ushort(lz);
            *reinterpret_cast<uint32_t*>(smemc + SB_AHI + off)     = hi0;
            *reinterpret_cast<uint32_t*>(smemc + SB_AHI + off + 4) = hi1;
            *reinterpret_cast<uint32_t*>(smemc + SB_ALO + off)     = lo0;
            *reinterpret_cast<uint32_t*>(smemc + SB_ALO + off + 4) = lo1;
        }

        // --- stage B chunk: Bsm[n][k] = W[kc*64+k][nc*128+n] -> bf16 hi/lo ---
        for (int idx = t; idx < 64 * 32; idx += 256) {
            int k  = idx >> 5;
            int n0 = (idx & 31) * 4;
            float4 v = *reinterpret_cast<const float4*>(
                &W[(kc * 64 + k) * 256 + nc * 128 + n0]);
            float vv[4] = {v.x, v.y, v.z, v.w};
#pragma unroll
            for (int j = 0; j < 4; j++) {
                __nv_bfloat16 h = __float2bfloat16_rn(vv[j]);
                __nv_bfloat16 l = __float2bfloat16_rn(vv[j] - __bfloat162float(h));
                uint32_t off = (uint32_t)((n0 + j) * 144 + k * 2);
                *reinterpret_cast<__nv_bfloat16*>(smemc + SB_BHI + off) = h;
                *reinterpret_cast<__nv_bfloat16*>(smemc + SB_BLO + off) = l;
            }
        }
        __syncthreads();

        // --- compute: 4 k-steps of 16 ---
#pragma unroll
        for (int ks = 0; ks < 4; ks++) {
            const uint32_t a_off = (uint32_t)(a_row * 144 + (ks * 16 + a_ksub) * 2);
            const uint32_t b_off = (uint32_t)(b_row * 144 + (ks * 16 + b_ksub) * 2);

            uint32_t ahi[2][4], alo[2][4];
#pragma unroll
            for (int mt = 0; mt < 2; mt++) {
                LDSM_X4(ahi[mt][0], ahi[mt][1], ahi[mt][2], ahi[mt][3],
                        sbase + SB_AHI + a_off + mt * 16 * 144);
                LDSM_X4(alo[mt][0], alo[mt][1], alo[mt][2], alo[mt][3],
                        sbase + SB_ALO + a_off + mt * 16 * 144);
            }
            uint32_t bhi[4][4], blo[4][4];
#pragma unroll
            for (int p = 0; p < 4; p++) {
                LDSM_X4(bhi[p][0], bhi[p][1], bhi[p][2], bhi[p][3],
                        sbase + SB_BHI + b_off + p * 16 * 144);
                LDSM_X4(blo[p][0], blo[p][1], blo[p][2], blo[p][3],
                        sbase + SB_BLO + b_off + p * 16 * 144);
            }
#pragma unroll
            for (int mt = 0; mt < 2; mt++)
#pragma unroll
                for (int nt = 0; nt < 8; nt++) {
                    const uint32_t* bh = &bhi[nt >> 1][(nt & 1) * 2];
                    const uint32_t* bl = &blo[nt >> 1][(nt & 1) * 2];
                    mma16816(acc[mt][nt], ahi[mt], bh);
                    mma16816(acc[mt][nt], ahi[mt], bl);
                    mma16816(acc[mt][nt], alo[mt], bh);
                }
        }
    }

    // --- epilogue: relu(+bias)*rho, reduce cols, per-row sums into smem ---
#pragma unroll
    for (int mt = 0; mt < 2; mt++) {
        float s0 = 0.0f, s1 = 0.0f;   // rows r and r+8
#pragma unroll
        for (int nt = 0; nt < 8; nt++) {
            int c = warp_n * 64 + nt * 8 + (lane & 3) * 2;
            float b0v = sb[c], b1v = sb[c + 1];
            float r0v = sr[c], r1v = sr[c + 1];
            s0 += fmaxf(acc[mt][nt][0] + b0v, 0.0f) * r0v;
            s0 += fmaxf(acc[mt][nt][1] + b1v, 0.0f) * r1v;
            s1 += fmaxf(acc[mt][nt][2] + b0v, 0.0f) * r0v;
            s1 += fmaxf(acc[mt][nt][3] + b1v, 0.0f) * r1v;
        }
        s0 += __shfl_xor_sync(0xffffffffu, s0, 1);
        s0 += __shfl_xor_sync(0xffffffffu, s0, 2);
        s1 += __shfl_xor_sync(0xffffffffu, s1, 1);
        s1 += __shfl_xor_sync(0xffffffffu, s1, 2);
        if ((lane & 3) == 0) {
            int row = warp_m * 32 + mt * 16 + (lane >> 2);
            atomicAdd(&s_arr[row], s0);
            atomicAdd(&s_arr[row + 8], s1);
        }
    }
    __syncthreads();

    // --- per-b group sums -> global atomicAdd ---
    {
        int bfirst = m0 / 5;
        int blast  = (m0 + 127) / 5;
        int ng = blast - bfirst + 1;
        if (t < ng) {
            int b = bfirst + t;
            float s = 0.0f;
#pragma unroll
            for (int r = 0; r < 5; r++) {
                int m = b * 5 + r;
                if (m >= m0 && m < m0 + 128) s += s_arr[m - m0];
            }
            atomicAdd(&out[br * B + b], s);
        }
    }
}

// ---------------------------------------------------------------------------
extern "C" void kernel_launch(void* const* d_in, const int* in_sizes, int n_in,
                              void* d_out, int out_size)
{
    const float* obs    = (const float*)d_in[0];
    const float* act    = (const float*)d_in[1];
    const float* ag     = (const float*)d_in[2];
    const float* g      = (const float*)d_in[3];
    const float* mp_w   = (const float*)d_in[4];
    const float* mp_b   = (const float*)d_in[5];
    const float* phi_w1 = (const float*)d_in[6];
    const float* phi_b1 = (const float*)d_in[7];
    const float* phi_w2 = (const float*)d_in[8];
    const float* phi_b2 = (const float*)d_in[9];
    const float* phi_w3 = (const float*)d_in[10];
    const float* phi_b3 = (const float*)d_in[11];
    const float* phi_w4 = (const float*)d_in[12];
    const float* phi_b4 = (const float*)d_in[13];
    const float* rho_w1 = (const float*)d_in[14];
    const float* rho_b1 = (const float*)d_in[15];
    const float* rho_w2 = (const float*)d_in[16];
    const float* rho_b2 = (const float*)d_in[17];
    float* out = (float*)d_out;

    const int B = in_sizes[1] / 4;  // act is (B,4)

    const int S1 = (46 * 128 + 8 * 20 * 48) * 4;      // 54,272 B
    const int S2 = (80 * SA_S + 157 * 128) * 4;       // 132,864 B
    cudaFuncSetAttribute(k_edge, cudaFuncAttributeMaxDynamicSharedMemorySize, S1);
    cudaFuncSetAttribute(k_phi1, cudaFuncAttributeMaxDynamicSharedMemorySize, S2);
    cudaFuncSetAttribute(k_phi2_mma, cudaFuncAttributeMaxDynamicSharedMemorySize, P2_SMEM);

    k_edge<<<B / 8, 256, S1>>>(obs, act, ag, g, mp_w, mp_b);
    k_phi1<<<dim3(B / 16, 4), 256, S2>>>(obs, act, phi_w1, phi_b1, phi_w3, phi_b3);
    k_init<<<(B + 255) / 256, 256>>>(out, rho_b1, rho_b2, B);
    k_phi2_mma<<<dim3(B * 5 / 128, 2, 2), 256, P2_SMEM>>>(
        phi_w2, phi_b2, phi_w4, phi_b4, rho_w1, rho_w2, out, B);
}

// round 4
// speedup vs baseline: 2.9489x; 2.4550x over previous
#include <cuda_runtime.h>
#include <cuda_bf16.h>
#include <cstdint>

// Problem constants (fixed by setup_inputs)
#define BMAX 16384
#define NROWS_MAX (BMAX * 5)

// ============================================================================
// Scratch (__device__ globals; no allocation allowed)
// ============================================================================
__device__ __nv_bfloat16 g_inp_hi[(size_t)NROWS_MAX * 160];  // 26 MB
__device__ __nv_bfloat16 g_inp_lo[(size_t)NROWS_MAX * 160];
__device__ __nv_bfloat16 g_h_hi[(size_t)NROWS_MAX * 512];    // 84 MB
__device__ __nv_bfloat16 g_h_lo[(size_t)NROWS_MAX * 512];
__device__ __nv_bfloat16 g_w1t_hi[512 * 160], g_w1t_lo[512 * 160];
__device__ __nv_bfloat16 g_w2t_hi[512 * 256], g_w2t_lo[512 * 256];

// ============================================================================
// Warp-MMA helpers (sm_80-era PTX: legal on compute_103, maps to HMMA)
// ============================================================================
#define LDSM_X4(r0, r1, r2, r3, addr) \
    asm volatile("ldmatrix.sync.aligned.m8n8.x4.shared.b16 {%0,%1,%2,%3}, [%4];" \
        : "=r"(r0), "=r"(r1), "=r"(r2), "=r"(r3) : "r"(addr))

__device__ __forceinline__ void mma16816(float* d, const uint32_t* a, const uint32_t* b) {
    asm volatile(
        "mma.sync.aligned.m16n8k16.row.col.f32.bf16.bf16.f32 "
        "{%0,%1,%2,%3}, {%4,%5,%6,%7}, {%8,%9}, {%0,%1,%2,%3};"
        : "+f"(d[0]), "+f"(d[1]), "+f"(d[2]), "+f"(d[3])
        : "r"(a[0]), "r"(a[1]), "r"(a[2]), "r"(a[3]), "r"(b[0]), "r"(b[1]));
}

__device__ __forceinline__ uint32_t smem_u32(const void* p) {
    uint32_t a;
    asm("{ .reg .u64 tmp; cvta.to.shared.u64 tmp, %1; cvt.u32.u64 %0, tmp; }"
        : "=r"(a) : "l"(p));
    return a;
}

__device__ __forceinline__ void split_bf16(float v, __nv_bfloat16& h, __nv_bfloat16& l) {
    h = __float2bfloat16_rn(v);
    l = __float2bfloat16_rn(v - __bfloat162float(h));
}

// ---------------------------------------------------------------------------
// K1: edge MLP + aggregation; writes agg as bf16 hi/lo into g_inp cols 29..156
// ---------------------------------------------------------------------------
__global__ __launch_bounds__(256) void k_edge(
    const float* __restrict__ obs, const float* __restrict__ act,
    const float* __restrict__ ag,  const float* __restrict__ g,
    const float* __restrict__ mp_w, const float* __restrict__ mp_b)
{
    extern __shared__ float smem[];
    float* sw   = smem;              // 46*128
    float* sinp = smem + 46 * 128;   // 8*20*48
    const int t  = threadIdx.x;
    const int b0 = blockIdx.x * 8;

    for (int i = t; i < 46 * 128; i += 256) sw[i] = mp_w[i];

    for (int idx = t; idx < 8 * 20 * 46; idx += 256) {
        int bl  = idx / 920;
        int rem = idx - bl * 920;
        int e   = rem / 46;
        int k   = rem - e * 46;
        int src = e >> 2, rr = e & 3;
        int dst = (rr < src) ? rr : rr + 1;
        int b   = b0 + bl;
        float v;
        if (k < 10)       v = obs[b * 85 + k];
        else if (k < 14)  v = act[b * 4 + (k - 10)];
        else if (k == 14) v = g[b * 30 + e]      - ag[b * 30 + e];
        else if (k == 15) v = g[b * 30 + e + 10] - ag[b * 30 + e + 10];
        else if (k < 31)  v = obs[b * 85 + 10 + src * 15 + (k - 16)];
        else              v = obs[b * 85 + 10 + dst * 15 + (k - 31)];
        sinp[(bl * 20 + e) * 48 + k] = v;
    }
    __syncthreads();

    const int nb = t & 31;
    const int bl = t >> 5;
    const int n0 = nb * 4;
    const float4 bias = *reinterpret_cast<const float4*>(mp_b + n0);
    const float4* sw4 = reinterpret_cast<const float4*>(sw);
    const float* ip = sinp + bl * 20 * 48;

    float acc[5][4];
#pragma unroll
    for (int i = 0; i < 5; i++)
#pragma unroll
        for (int c = 0; c < 4; c++) acc[i][c] = 0.0f;

#pragma unroll
    for (int e = 0; e < 20; e++) {
        const int src = e >> 2, rr = e & 3;
        const int dst = (rr < src) ? rr : rr + 1;
        float4 s = bias;
        const float* ipe = ip + e * 48;
#pragma unroll 2
        for (int k = 0; k < 46; k++) {
            float  a = ipe[k];
            float4 w = sw4[k * 32 + nb];
            s.x += a * w.x; s.y += a * w.y; s.z += a * w.z; s.w += a * w.w;
        }
        acc[dst][0] += fmaxf(s.x, 0.0f);
        acc[dst][1] += fmaxf(s.y, 0.0f);
        acc[dst][2] += fmaxf(s.z, 0.0f);
        acc[dst][3] += fmaxf(s.w, 0.0f);
    }

    const int b = b0 + bl;
#pragma unroll
    for (int i = 0; i < 5; i++) {
        size_t base = (size_t)(b * 5 + i) * 160 + 29 + n0;
#pragma unroll
        for (int c = 0; c < 4; c++) {
            __nv_bfloat16 h, l;
            split_bf16(acc[i][c], h, l);
            g_inp_hi[base + c] = h;
            g_inp_lo[base + c] = l;
        }
    }
}

// ---------------------------------------------------------------------------
// K-prep: fill g_inp cols 0..28 (act,body,obj) and zero cols 157..159
// ---------------------------------------------------------------------------
__global__ void k_prep(const float* __restrict__ obs, const float* __restrict__ act,
                       int nrows)
{
    int idx = blockIdx.x * 256 + threadIdx.x;
    int row = idx >> 5;
    int c   = idx & 31;
    if (row >= nrows) return;
    int b = row / 5;
    int n = row - b * 5;
    float v; int col;
    if (c < 4)       { v = act[b * 4 + c];                       col = c; }
    else if (c < 14) { v = obs[b * 85 + (c - 4)];                col = c; }
    else if (c < 29) { v = obs[b * 85 + 10 + n * 15 + (c - 14)]; col = c; }
    else             { v = 0.0f;                                  col = 128 + c; } // 157..159
    __nv_bfloat16 h, l;
    split_bf16(v, h, l);
    g_inp_hi[(size_t)row * 160 + col] = h;
    g_inp_lo[(size_t)row * 160 + col] = l;
}

// ---------------------------------------------------------------------------
// K-wconv: transpose + bf16-split weights.
//   g_w1t[n][k] (n=512: W1|W3, k=160 padded from 157)
//   g_w2t[n][k] (n=512: W2|W4, k=256)
// ---------------------------------------------------------------------------
__global__ void k_wconv(const float* __restrict__ w1, const float* __restrict__ w3,
                        const float* __restrict__ w2, const float* __restrict__ w4)
{
    int idx = blockIdx.x * 256 + threadIdx.x;
    const int N1 = 512 * 160;
    const int N2 = 512 * 256;
    if (idx < N1) {
        int n = idx / 160, k = idx - n * 160;
        float v = 0.0f;
        if (k < 157) v = (n < 256) ? w1[k * 256 + n] : w3[k * 256 + (n - 256)];
        __nv_bfloat16 h, l;
        split_bf16(v, h, l);
        g_w1t_hi[idx] = h; g_w1t_lo[idx] = l;
    } else if (idx < N1 + N2) {
        int j = idx - N1;
        int n = j / 256, k = j - n * 256;
        float v = (n < 256) ? w2[k * 256 + n] : w4[k * 256 + (n - 256)];
        __nv_bfloat16 h, l;
        split_bf16(v, h, l);
        g_w2t_hi[j] = h; g_w2t_lo[j] = l;
    }
}

// ---------------------------------------------------------------------------
// K-init: out[b] = rho_b
// ---------------------------------------------------------------------------
__global__ void k_init(float* __restrict__ out,
                       const float* __restrict__ rb1, const float* __restrict__ rb2, int B)
{
    int i = blockIdx.x * 256 + threadIdx.x;
    if (i < B) { out[i] = rb1[0]; out[B + i] = rb2[0]; }
}

// ---------------------------------------------------------------------------
// K-phi1 (MMA): D[128m x 128n] = inp-tile @ w1t-block, K=160 (5 chunks of 32).
// 8 warps 4Mx2N, warp tile m32 x n64. Epilogue: relu(D+bias) -> g_h hi/lo bf16.
// SMEM: bias 0..512; A_hi 512 (128x80B); A_lo 10752; B_hi 20992; B_lo 31232.
// ---------------------------------------------------------------------------
#define P1_BIAS 0
#define P1_AHI  512
#define P1_ALO  10752
#define P1_BHI  20992
#define P1_BLO  31232
#define P1_SMEM 41472

__global__ __launch_bounds__(256, 2) void k_phi1_mma(
    const float* __restrict__ phi_b1, const float* __restrict__ phi_b3)
{
    extern __shared__ char smemc[];
    const uint32_t sbase = smem_u32(smemc);
    const int t    = threadIdx.x;
    const int wid  = t >> 5;
    const int lane = t & 31;
    const int m0   = blockIdx.x * 128;
    const int nc   = blockIdx.y;            // which 128 of N=512

    float* sb = reinterpret_cast<float*>(smemc + P1_BIAS);
    if (t < 128) {
        int n = nc * 128 + t;
        sb[t] = (n < 256) ? phi_b1[n] : phi_b3[n - 256];
    }

    const int warp_m = wid & 3;
    const int warp_n = wid >> 2;

    float acc[2][8][4];
#pragma unroll
    for (int mt = 0; mt < 2; mt++)
#pragma unroll
        for (int nt = 0; nt < 8; nt++)
#pragma unroll
            for (int j = 0; j < 4; j++) acc[mt][nt][j] = 0.0f;

    const int a_row  = warp_m * 32 + (lane & 15);
    const int a_ksub = (lane >> 4) * 8;
    const int b_row  = warp_n * 64 + (lane & 7) + ((lane >> 4) & 1) * 8;
    const int b_ksub = ((lane >> 3) & 1) * 8;

    for (int kc = 0; kc < 5; kc++) {
        __syncthreads();
        // stage A chunk: g_inp[(m0+row)*160 + kc*32 ..+32] -> smem stride 80B
        for (int idx = t; idx < 128 * 4; idx += 256) {
            int row = idx >> 2, q = idx & 3;
            const uint4* sh = reinterpret_cast<const uint4*>(
                g_inp_hi + (size_t)(m0 + row) * 160 + kc * 32) + q;
            const uint4* sl = reinterpret_cast<const uint4*>(
                g_inp_lo + (size_t)(m0 + row) * 160 + kc * 32) + q;
            *reinterpret_cast<uint4*>(smemc + P1_AHI + row * 80 + q * 16) = *sh;
            *reinterpret_cast<uint4*>(smemc + P1_ALO + row * 80 + q * 16) = *sl;
        }
        // stage B chunk: g_w1t[(nc*128+n)*160 + kc*32 ..]
        for (int idx = t; idx < 128 * 4; idx += 256) {
            int n = idx >> 2, q = idx & 3;
            const uint4* sh = reinterpret_cast<const uint4*>(
                g_w1t_hi + (size_t)(nc * 128 + n) * 160 + kc * 32) + q;
            const uint4* sl = reinterpret_cast<const uint4*>(
                g_w1t_lo + (size_t)(nc * 128 + n) * 160 + kc * 32) + q;
            *reinterpret_cast<uint4*>(smemc + P1_BHI + n * 80 + q * 16) = *sh;
            *reinterpret_cast<uint4*>(smemc + P1_BLO + n * 80 + q * 16) = *sl;
        }
        __syncthreads();

#pragma unroll
        for (int ks = 0; ks < 2; ks++) {
            const uint32_t a_off = (uint32_t)(a_row * 80 + (ks * 16 + a_ksub) * 2);
            const uint32_t b_off = (uint32_t)(b_row * 80 + (ks * 16 + b_ksub) * 2);
            uint32_t ahi[2][4], alo[2][4];
#pragma unroll
            for (int mt = 0; mt < 2; mt++) {
                LDSM_X4(ahi[mt][0], ahi[mt][1], ahi[mt][2], ahi[mt][3],
                        sbase + P1_AHI + a_off + mt * 16 * 80);
                LDSM_X4(alo[mt][0], alo[mt][1], alo[mt][2], alo[mt][3],
                        sbase + P1_ALO + a_off + mt * 16 * 80);
            }
#pragma unroll
            for (int p = 0; p < 4; p++) {
                uint32_t bh[4], bl[4];
                LDSM_X4(bh[0], bh[1], bh[2], bh[3],
                        sbase + P1_BHI + b_off + p * 16 * 80);
                LDSM_X4(bl[0], bl[1], bl[2], bl[3],
                        sbase + P1_BLO + b_off + p * 16 * 80);
#pragma unroll
                for (int mt = 0; mt < 2; mt++)
#pragma unroll
                    for (int hh = 0; hh < 2; hh++) {
                        mma16816(acc[mt][p * 2 + hh], ahi[mt], &bh[hh * 2]);
                        mma16816(acc[mt][p * 2 + hh], ahi[mt], &bl[hh * 2]);
                        mma16816(acc[mt][p * 2 + hh], alo[mt], &bh[hh * 2]);
                    }
            }
        }
    }

    // epilogue: relu(+bias), split to hi/lo bf16, store to g_h (col = nc*128+c)
#pragma unroll
    for (int mt = 0; mt < 2; mt++)
#pragma unroll
        for (int nt = 0; nt < 8; nt++) {
            int c = warp_n * 64 + nt * 8 + (lane & 3) * 2;
            float b0 = sb[c], b1 = sb[c + 1];
#pragma unroll
            for (int half = 0; half < 2; half++) {
                int row = warp_m * 32 + mt * 16 + (lane >> 2) + half * 8;
                float v0 = fmaxf(acc[mt][nt][half * 2]     + b0, 0.0f);
                float v1 = fmaxf(acc[mt][nt][half * 2 + 1] + b1, 0.0f);
                __nv_bfloat16 h0, l0, h1, l1;
                split_bf16(v0, h0, l0);
                split_bf16(v1, h1, l1);
                uint32_t ph = ((uint32_t)__bfloat16_as_ushort(h1) << 16) | __bfloat16_as_ushort(h0);
                uint32_t pl = ((uint32_t)__bfloat16_as_ushort(l1) << 16) | __bfloat16_as_ushort(l0);
                size_t off = (size_t)(m0 + row) * 512 + nc * 128 + c;
                *reinterpret_cast<uint32_t*>(g_h_hi + off) = ph;
                *reinterpret_cast<uint32_t*>(g_h_lo + off) = pl;
            }
        }
}

// ---------------------------------------------------------------------------
// K-phi2 (MMA): D[128m x 128n] = h-tile @ w2t-block, K=256 (4 chunks of 64).
// Fused epilogue: q += sum relu(D+bias)*rho -> atomicAdd per b.
// SMEM: bias 0, rho 512, s_arr 1024, A_hi 1536 (128x144B), A_lo 19968,
//       B_hi 38400, B_lo 56832; total 75264.
// ---------------------------------------------------------------------------
#define SB_BIAS 0
#define SB_RHO  512
#define SB_SARR 1024
#define SB_AHI  1536
#define SB_ALO  19968
#define SB_BHI  38400
#define SB_BLO  56832
#define P2_SMEM 75264

__global__ __launch_bounds__(256, 2) void k_phi2_mma(
    const float* __restrict__ phi_b2, const float* __restrict__ phi_b4,
    const float* __restrict__ rho_w1, const float* __restrict__ rho_w2,
    float* __restrict__ out, int B)
{
    extern __shared__ char smemc[];
    const uint32_t sbase = smem_u32(smemc);
    const int t    = threadIdx.x;
    const int wid  = t >> 5;
    const int lane = t & 31;
    const int m0   = blockIdx.x * 128;
    const int br   = blockIdx.y;
    const int nc   = blockIdx.z;

    const float* bias = br ? phi_b4 : phi_b2;
    const float* rho  = br ? rho_w2 : rho_w1;

    float* sb    = reinterpret_cast<float*>(smemc + SB_BIAS);
    float* sr    = reinterpret_cast<float*>(smemc + SB_RHO);
    float* s_arr = reinterpret_cast<float*>(smemc + SB_SARR);

    if (t < 128) {
        sb[t] = bias[nc * 128 + t];
        sr[t] = rho[nc * 128 + t];
        s_arr[t] = 0.0f;
    }

    const int warp_m = wid & 3;
    const int warp_n = wid >> 2;

    float acc[2][8][4];
#pragma unroll
    for (int mt = 0; mt < 2; mt++)
#pragma unroll
        for (int nt = 0; nt < 8; nt++)
#pragma unroll
            for (int j = 0; j < 4; j++) acc[mt][nt][j] = 0.0f;

    const int a_row  = warp_m * 32 + (lane & 15);
    const int a_ksub = (lane >> 4) * 8;
    const int b_row  = warp_n * 64 + (lane & 7) + ((lane >> 4) & 1) * 8;
    const int b_ksub = ((lane >> 3) & 1) * 8;

    for (int kc = 0; kc < 4; kc++) {
        __syncthreads();
        // stage A: g_h[(m0+row)*512 + br*256 + kc*64 ..+64]  (128B contiguous)
        for (int idx = t; idx < 128 * 8; idx += 256) {
            int row = idx >> 3, q = idx & 7;
            const uint4* sh = reinterpret_cast<const uint4*>(
                g_h_hi + (size_t)(m0 + row) * 512 + br * 256 + kc * 64) + q;
            const uint4* sl = reinterpret_cast<const uint4*>(
                g_h_lo + (size_t)(m0 + row) * 512 + br * 256 + kc * 64) + q;
            *reinterpret_cast<uint4*>(smemc + SB_AHI + row * 144 + q * 16) = *sh;
            *reinterpret_cast<uint4*>(smemc + SB_ALO + row * 144 + q * 16) = *sl;
        }
        // stage B: g_w2t[(br*256 + nc*128 + n)*256 + kc*64 ..]
        for (int idx = t; idx < 128 * 8; idx += 256) {
            int n = idx >> 3, q = idx & 7;
            const uint4* sh = reinterpret_cast<const uint4*>(
                g_w2t_hi + (size_t)(br * 256 + nc * 128 + n) * 256 + kc * 64) + q;
            const uint4* sl = reinterpret_cast<const uint4*>(
                g_w2t_lo + (size_t)(br * 256 + nc * 128 + n) * 256 + kc * 64) + q;
            *reinterpret_cast<uint4*>(smemc + SB_BHI + n * 144 + q * 16) = *sh;
            *reinterpret_cast<uint4*>(smemc + SB_BLO + n * 144 + q * 16) = *sl;
        }
        __syncthreads();

#pragma unroll
        for (int ks = 0; ks < 4; ks++) {
            const uint32_t a_off = (uint32_t)(a_row * 144 + (ks * 16 + a_ksub) * 2);
            const uint32_t b_off = (uint32_t)(b_row * 144 + (ks * 16 + b_ksub) * 2);
            uint32_t ahi[2][4], alo[2][4];
#pragma unroll
            for (int mt = 0; mt < 2; mt++) {
                LDSM_X4(ahi[mt][0], ahi[mt][1], ahi[mt][2], ahi[mt][3],
                        sbase + SB_AHI + a_off + mt * 16 * 144);
                LDSM_X4(alo[mt][0], alo[mt][1], alo[mt][2], alo[mt][3],
                        sbase + SB_ALO + a_off + mt * 16 * 144);
            }
#pragma unroll
            for (int p = 0; p < 4; p++) {
                uint32_t bh[4], bl[4];
                LDSM_X4(bh[0], bh[1], bh[2], bh[3],
                        sbase + SB_BHI + b_off + p * 16 * 144);
                LDSM_X4(bl[0], bl[1], bl[2], bl[3],
                        sbase + SB_BLO + b_off + p * 16 * 144);
#pragma unroll
                for (int mt = 0; mt < 2; mt++)
#pragma unroll
                    for (int hh = 0; hh < 2; hh++) {
                        mma16816(acc[mt][p * 2 + hh], ahi[mt], &bh[hh * 2]);
                        mma16816(acc[mt][p * 2 + hh], ahi[mt], &bl[hh * 2]);
                        mma16816(acc[mt][p * 2 + hh], alo[mt], &bh[hh * 2]);
                    }
            }
        }
    }

    // epilogue: relu(+bias)*rho, reduce cols, per-row sums into smem
#pragma unroll
    for (int mt = 0; mt < 2; mt++) {
        float s0 = 0.0f, s1 = 0.0f;
#pragma unroll
        for (int nt = 0; nt < 8; nt++) {
            int c = warp_n * 64 + nt * 8 + (lane & 3) * 2;
            float b0v = sb[c], b1v = sb[c + 1];
            float r0v = sr[c], r1v = sr[c + 1];
            s0 += fmaxf(acc[mt][nt][0] + b0v, 0.0f) * r0v;
            s0 += fmaxf(acc[mt][nt][1] + b1v, 0.0f) * r1v;
            s1 += fmaxf(acc[mt][nt][2] + b0v, 0.0f) * r0v;
            s1 += fmaxf(acc[mt][nt][3] + b1v, 0.0f) * r1v;
        }
        s0 += __shfl_xor_sync(0xffffffffu, s0, 1);
        s0 += __shfl_xor_sync(0xffffffffu, s0, 2);
        s1 += __shfl_xor_sync(0xffffffffu, s1, 1);
        s1 += __shfl_xor_sync(0xffffffffu, s1, 2);
        if ((lane & 3) == 0) {
            int row = warp_m * 32 + mt * 16 + (lane >> 2);
            atomicAdd(&s_arr[row], s0);
            atomicAdd(&s_arr[row + 8], s1);
        }
    }
    __syncthreads();

    {
        int bfirst = m0 / 5;
        int blast  = (m0 + 127) / 5;
        int ng = blast - bfirst + 1;
        if (t < ng) {
            int b = bfirst + t;
            float s = 0.0f;
#pragma unroll
            for (int r = 0; r < 5; r++) {
                int m = b * 5 + r;
                if (m >= m0 && m < m0 + 128) s += s_arr[m - m0];
            }
            atomicAdd(&out[br * B + b], s);
        }
    }
}

// ---------------------------------------------------------------------------
extern "C" void kernel_launch(void* const* d_in, const int* in_sizes, int n_in,
                              void* d_out, int out_size)
{
    const float* obs    = (const float*)d_in[0];
    const float* act    = (const float*)d_in[1];
    const float* ag     = (const float*)d_in[2];
    const float* g      = (const float*)d_in[3];
    const float* mp_w   = (const float*)d_in[4];
    const float* mp_b   = (const float*)d_in[5];
    const float* phi_w1 = (const float*)d_in[6];
    const float* phi_b1 = (const float*)d_in[7];
    const float* phi_w2 = (const float*)d_in[8];
    const float* phi_b2 = (const float*)d_in[9];
    const float* phi_w3 = (const float*)d_in[10];
    const float* phi_b3 = (const float*)d_in[11];
    const float* phi_w4 = (const float*)d_in[12];
    const float* phi_b4 = (const float*)d_in[13];
    const float* rho_w1 = (const float*)d_in[14];
    const float* rho_b1 = (const float*)d_in[15];
    const float* rho_w2 = (const float*)d_in[16];
    const float* rho_b2 = (const float*)d_in[17];
    float* out = (float*)d_out;

    const int B = in_sizes[1] / 4;  // act is (B,4)
    const int nrows = B * 5;

    const int S1 = (46 * 128 + 8 * 20 * 48) * 4;      // 54,272 B
    cudaFuncSetAttribute(k_edge, cudaFuncAttributeMaxDynamicSharedMemorySize, S1);
    cudaFuncSetAttribute(k_phi1_mma, cudaFuncAttributeMaxDynamicSharedMemorySize, P1_SMEM);
    cudaFuncSetAttribute(k_phi2_mma, cudaFuncAttributeMaxDynamicSharedMemorySize, P2_SMEM);

    k_edge<<<B / 8, 256, S1>>>(obs, act, ag, g, mp_w, mp_b);
    k_prep<<<(nrows * 32 + 255) / 256, 256>>>(obs, act, nrows);
    k_wconv<<<(512 * 160 + 512 * 256 + 255) / 256, 256>>>(phi_w1, phi_w3, phi_w2, phi_w4);
    k_phi1_mma<<<dim3(nrows / 128, 4), 256, P1_SMEM>>>(phi_b1, phi_b3);
    k_init<<<(B + 255) / 256, 256>>>(out, rho_b1, rho_b2, B);
    k_phi2_mma<<<dim3(nrows / 128, 2, 2), 256, P2_SMEM>>>(
        phi_b2, phi_b4, rho_w1, rho_w2, out, B);
}